// round 10
// baseline (speedup 1.0000x reference)
#include <cuda_runtime.h>
#include <cuda_fp16.h>
#include <cstdint>

// Problem constants (fixed by the dataset)
#define N_NODES 100000
#define N_EDGES 800000
#define IN_SIZE 128
#define OUT_SIZE 64

// ---------------------------------------------------------------------------
// Scratch (no cudaMalloc allowed)
// ---------------------------------------------------------------------------
__device__ int   g_is64;
__device__ int   g_rowptr[N_NODES + 1];
// fp16 intermediate activations: [node][32] half2  (64 cols = 128 B/row)
__device__ __align__(16) __half2 g_h0[(size_t)N_NODES * 32];
__device__ __align__(16) __half2 g_h1[(size_t)N_NODES * 32];

// ---------------------------------------------------------------------------
// 1) Detect int64 vs int32 indices (warp-parallel, one ballot).
// ---------------------------------------------------------------------------
__global__ void detect_kernel(const void* src_any) {
    const long long v = ((const long long*)src_any)[threadIdx.x & 31];
    const bool ok = (v >= 0 && v < (long long)N_NODES);
    const unsigned m = __ballot_sync(0xffffffffu, ok);
    if (threadIdx.x == 0) g_is64 = (m == 0xffffffffu) ? 1 : 0;
}

// ---------------------------------------------------------------------------
// 2) row_ptr via per-node lower_bound directly on the ORIGINAL sorted tgt
//    array (uniform is64 branch) — no conversion pass needed.
// ---------------------------------------------------------------------------
__global__ void rowptr_kernel(const void* tgt_any) {
    const int t = blockIdx.x * blockDim.x + threadIdx.x;
    if (t > N_NODES) return;
    int lo = 0, hi = N_EDGES;
    if (g_is64) {
        const long long* tgt = (const long long*)tgt_any;
        const long long tv = t;
        while (lo < hi) {
            const int mid = (lo + hi) >> 1;
            if (__ldg(&tgt[mid]) < tv) lo = mid + 1; else hi = mid;
        }
    } else {
        const int* tgt = (const int*)tgt_any;
        while (lo < hi) {
            const int mid = (lo + hi) >> 1;
            if (__ldg(&tgt[mid]) < t) lo = mid + 1; else hi = mid;
        }
    }
    g_rowptr[t] = lo;
}

// ---------------------------------------------------------------------------
// 3) GEMM via HMMA tensor cores: Y = X @ W + b -> fp16 store.
//    256 threads / block (8 warps x 16-row warp tile) on a 128-row block tile
//    for 2x the occupancy of the R7 version (latency-bound on X DRAM reads).
// ---------------------------------------------------------------------------
#define XS_HALVES (128 * 128)   // 32768 B
#define WS_HALVES (128 * 64)    // 16384 B

__global__ __launch_bounds__(256) void gemm_kernel(const float* __restrict__ X,
                                                   const float* __restrict__ W,
                                                   const float* __restrict__ b) {
    __shared__ __half Xs[XS_HALVES];   // [row][k], swizzled 16B chunks
    __shared__ __half Ws[WS_HALVES];   // [k][n],  swizzled 16B chunks

    const int tid    = threadIdx.x;
    const int lane   = tid & 31;
    const int warpId = tid >> 5;       // 0..7
    const int rowBase = blockIdx.x * 128;

    // ---- stage X: 128x128 fp32 -> fp16, swizzled. 16 float4 per thread ----
    #pragma unroll
    for (int i = 0; i < 16; ++i) {
        const int linear = tid + 256 * i;      // 0..4095
        const int row = linear >> 5;           // 0..127
        const int c   = linear & 31;           // float4 col
        const int gr  = rowBase + row;
        float4 v = (gr < N_NODES) ? __ldg((const float4*)&X[(size_t)gr * IN_SIZE + 4 * c])
                                  : make_float4(0.f, 0.f, 0.f, 0.f);
        __align__(8) __half2 h[2];
        h[0] = __floats2half2_rn(v.x, v.y);
        h[1] = __floats2half2_rn(v.z, v.w);
        const int chunk = ((c >> 1) ^ (row & 7));
        *(uint2*)&Xs[row * 128 + chunk * 8 + 4 * (c & 1)] = *(const uint2*)h;
    }

    // ---- stage W: 128x64 fp32 -> fp16, swizzled. 8 float4 per thread ----
    #pragma unroll
    for (int i = 0; i < 8; ++i) {
        const int linear = tid + 256 * i;      // 0..2047
        const int k = linear >> 4;             // 0..127
        const int c = linear & 15;             // float4 col
        float4 v = __ldg((const float4*)&W[(size_t)k * OUT_SIZE + 4 * c]);
        __align__(8) __half2 h[2];
        h[0] = __floats2half2_rn(v.x, v.y);
        h[1] = __floats2half2_rn(v.z, v.w);
        const int chunk = ((c >> 1) ^ (k & 7));
        *(uint2*)&Ws[k * 64 + chunk * 8 + 4 * (c & 1)] = *(const uint2*)h;
    }
    __syncthreads();

    // ---- mma mainloop: warp tile 16 rows x 64 cols ----
    const int wr = warpId * 16;
    float d[8][4];
    #pragma unroll
    for (int nt = 0; nt < 8; ++nt)
        #pragma unroll
        for (int q = 0; q < 4; ++q) d[nt][q] = 0.f;

    #pragma unroll
    for (int ks = 0; ks < 8; ++ks) {
        unsigned a[4];
        {
            const int row = wr + (lane & 15);
            const int chunk = (ks * 2 + (lane >> 4)) ^ (row & 7);
            const unsigned addr =
                (unsigned)__cvta_generic_to_shared(&Xs[row * 128 + chunk * 8]);
            asm volatile("ldmatrix.sync.aligned.m8n8.x4.shared.b16 {%0,%1,%2,%3}, [%4];"
                         : "=r"(a[0]), "=r"(a[1]), "=r"(a[2]), "=r"(a[3])
                         : "r"(addr));
        }
        #pragma unroll
        for (int np = 0; np < 4; ++np) {
            const int k = ks * 16 + (lane & 7) + ((lane >> 3) & 1) * 8;
            const int chunk = (np * 2 + (lane >> 4)) ^ (k & 7);
            const unsigned addr =
                (unsigned)__cvta_generic_to_shared(&Ws[k * 64 + chunk * 8]);
            unsigned bf[4];
            asm volatile("ldmatrix.sync.aligned.m8n8.x4.trans.shared.b16 {%0,%1,%2,%3}, [%4];"
                         : "=r"(bf[0]), "=r"(bf[1]), "=r"(bf[2]), "=r"(bf[3])
                         : "r"(addr));
            asm volatile(
                "mma.sync.aligned.m16n8k16.row.col.f32.f16.f16.f32 "
                "{%0,%1,%2,%3}, {%4,%5,%6,%7}, {%8,%9}, {%0,%1,%2,%3};"
                : "+f"(d[2 * np][0]), "+f"(d[2 * np][1]),
                  "+f"(d[2 * np][2]), "+f"(d[2 * np][3])
                : "r"(a[0]), "r"(a[1]), "r"(a[2]), "r"(a[3]),
                  "r"(bf[0]), "r"(bf[1]));
            asm volatile(
                "mma.sync.aligned.m16n8k16.row.col.f32.f16.f16.f32 "
                "{%0,%1,%2,%3}, {%4,%5,%6,%7}, {%8,%9}, {%0,%1,%2,%3};"
                : "+f"(d[2 * np + 1][0]), "+f"(d[2 * np + 1][1]),
                  "+f"(d[2 * np + 1][2]), "+f"(d[2 * np + 1][3])
                : "r"(a[0]), "r"(a[1]), "r"(a[2]), "r"(a[3]),
                  "r"(bf[2]), "r"(bf[3]));
        }
    }

    // ---- epilogue: bias + fp16 store ----
    float2 bias2[8];
    #pragma unroll
    for (int nt = 0; nt < 8; ++nt)
        bias2[nt] = __ldg(&((const float2*)b)[nt * 4 + (lane & 3)]);

    const int r0 = rowBase + wr + (lane >> 2);
    const int r1 = r0 + 8;
    #pragma unroll
    for (int nt = 0; nt < 8; ++nt) {
        const int h2idx = nt * 4 + (lane & 3);
        if (r0 < N_NODES)
            g_h0[(size_t)r0 * 32 + h2idx] =
                __floats2half2_rn(d[nt][0] + bias2[nt].x, d[nt][1] + bias2[nt].y);
        if (r1 < N_NODES)
            g_h0[(size_t)r1 * 32 + h2idx] =
                __floats2half2_rn(d[nt][2] + bias2[nt].x, d[nt][3] + bias2[nt].y);
    }
}

// accumulate 8 halves (one uint4) into float[8]
__device__ __forceinline__ void acc16(float* a, uint4 u) {
    const float2 f0 = __half22float2(*reinterpret_cast<__half2*>(&u.x));
    const float2 f1 = __half22float2(*reinterpret_cast<__half2*>(&u.y));
    const float2 f2 = __half22float2(*reinterpret_cast<__half2*>(&u.z));
    const float2 f3 = __half22float2(*reinterpret_cast<__half2*>(&u.w));
    a[0] += f0.x; a[1] += f0.y; a[2] += f1.x; a[3] += f1.y;
    a[4] += f2.x; a[5] += f2.y; a[6] += f3.x; a[7] += f3.y;
}

// ---------------------------------------------------------------------------
// 4) Propagation: FOUR nodes per warp (quarter-warp of 8 lanes per node).
//    Each lane loads uint4 (16 B) of its node's 128 B fp16 row: no shuffles,
//    4x fewer warps, wide loads. Src indices read directly from the original
//    buffer (uniform is64 branch), software-pipelined ahead of the gathers.
//    new[t] = (deg>0) ? (in[t] + sum in[src[e]]) / (deg+1) : 0
//    stage 0: g_h0 -> g_h1 (fp16);  stage 1: g_h1 -> d_out (fp32, ReLU)
// ---------------------------------------------------------------------------
__global__ __launch_bounds__(256) void prop_kernel(const void* __restrict__ src_any,
                                                   float* __restrict__ dout, int stage) {
    const int gw   = (blockIdx.x * blockDim.x + threadIdx.x) >> 5;
    const int lane = threadIdx.x & 31;
    const int q    = lane >> 3;        // quarter 0..3
    const int ln8  = lane & 7;         // lane within quarter
    const int t    = gw * 4 + q;
    if (t >= N_NODES) return;

    const uint4* __restrict__ in = (stage == 0) ? (const uint4*)g_h0 : (const uint4*)g_h1;
    const int is64 = g_is64;
    const long long* __restrict__ s64 = (const long long*)src_any;
    const int*       __restrict__ s32 = (const int*)src_any;

    const int start = __ldg(&g_rowptr[t]);
    const int end   = __ldg(&g_rowptr[t + 1]);
    const int deg   = end - start;

    float a[8] = {0.f, 0.f, 0.f, 0.f, 0.f, 0.f, 0.f, 0.f};

    if (deg > 0) {
        int e = start;
        // software pipeline: index for next iteration loads during gather
        int s_cur = is64 ? (int)__ldg(&s64[e]) : __ldg(&s32[e]);
        for (; e + 1 < end; ++e) {
            const int s_nxt = is64 ? (int)__ldg(&s64[e + 1]) : __ldg(&s32[e + 1]);
            acc16(a, __ldg(&in[(size_t)s_cur * 8 + ln8]));
            s_cur = s_nxt;
        }
        acc16(a, __ldg(&in[(size_t)s_cur * 8 + ln8]));

        // own contribution + scale
        acc16(a, __ldg(&in[(size_t)t * 8 + ln8]));
        const float sc = 1.0f / (float)(deg + 1);
        #pragma unroll
        for (int i = 0; i < 8; ++i) a[i] *= sc;
    }
    // deg==0: a stays zero

    if (stage == 0) {
        __align__(16) __half2 h[4];
        h[0] = __floats2half2_rn(a[0], a[1]);
        h[1] = __floats2half2_rn(a[2], a[3]);
        h[2] = __floats2half2_rn(a[4], a[5]);
        h[3] = __floats2half2_rn(a[6], a[7]);
        ((uint4*)g_h1)[(size_t)t * 8 + ln8] = *(const uint4*)h;
    } else {
        #pragma unroll
        for (int i = 0; i < 8; ++i) a[i] = fmaxf(a[i], 0.f);
        *(float4*)&dout[(size_t)t * 64 + ln8 * 8]     = make_float4(a[0], a[1], a[2], a[3]);
        *(float4*)&dout[(size_t)t * 64 + ln8 * 8 + 4] = make_float4(a[4], a[5], a[6], a[7]);
    }
}

// ---------------------------------------------------------------------------
// Launch. Inputs (metadata order): data, W, b, src_idx, tgt_idx
// ---------------------------------------------------------------------------
extern "C" void kernel_launch(void* const* d_in, const int* in_sizes, int n_in,
                              void* d_out, int out_size) {
    const float* X = (const float*)d_in[0];
    const float* W = (const float*)d_in[1];
    const float* b = (const float*)d_in[2];
    const void*  src = d_in[3];
    const void*  tgt = d_in[4];
    float* out = (float*)d_out;

    detect_kernel<<<1, 32>>>(src);
    rowptr_kernel<<<(N_NODES + 1 + 255) / 256, 256>>>(tgt);
    gemm_kernel<<<(N_NODES + 127) / 128, 256>>>(X, W, b);
    // 4 nodes per warp -> N_NODES/4 warps -> /8 warps per block
    const int propBlocks = (N_NODES + 31) / 32;   // 3125 blocks of 256 threads
    prop_kernel<<<propBlocks, 256>>>(src, out, 0);
    prop_kernel<<<propBlocks, 256>>>(src, out, 1);
}

// round 11
// speedup vs baseline: 1.5000x; 1.5000x over previous
#include <cuda_runtime.h>
#include <cuda_fp16.h>
#include <cstdint>

// Problem constants (fixed by the dataset)
#define N_NODES 100000
#define N_EDGES 800000
#define IN_SIZE 128
#define OUT_SIZE 64

// ---------------------------------------------------------------------------
// Scratch (no cudaMalloc allowed)
// ---------------------------------------------------------------------------
__device__ int   g_rowptr[N_NODES + 1];
// fp16 intermediate activations: [node][32] half2  (64 cols = 128 B/row)
__device__ __align__(16) __half2 g_h0[(size_t)N_NODES * 32];
__device__ __align__(16) __half2 g_h1[(size_t)N_NODES * 32];

// ---------------------------------------------------------------------------
// Per-warp int64-vs-int32 detection: one broadcast load + ballot.
// src_idx is uniform random in [0, N_NODES); int32 data read as int64 pairs
// two values -> out of range almost surely within 32 samples.
// Must be called with ALL 32 lanes active.
// ---------------------------------------------------------------------------
__device__ __forceinline__ int warp_detect64(const void* src_any) {
    const long long v = __ldg(&((const long long*)src_any)[threadIdx.x & 31]);
    const bool ok = (v >= 0 && v < (long long)N_NODES);
    return (__ballot_sync(0xffffffffu, ok) == 0xffffffffu) ? 1 : 0;
}

// ---------------------------------------------------------------------------
// 1) row_ptr via per-node lower_bound directly on the ORIGINAL sorted tgt.
// ---------------------------------------------------------------------------
__global__ void rowptr_kernel(const void* src_any, const void* tgt_any) {
    const int is64 = warp_detect64(src_any);
    const int t = blockIdx.x * blockDim.x + threadIdx.x;
    if (t > N_NODES) return;
    int lo = 0, hi = N_EDGES;
    if (is64) {
        const long long* tgt = (const long long*)tgt_any;
        const long long tv = t;
        while (lo < hi) {
            const int mid = (lo + hi) >> 1;
            if (__ldg(&tgt[mid]) < tv) lo = mid + 1; else hi = mid;
        }
    } else {
        const int* tgt = (const int*)tgt_any;
        while (lo < hi) {
            const int mid = (lo + hi) >> 1;
            if (__ldg(&tgt[mid]) < t) lo = mid + 1; else hi = mid;
        }
    }
    g_rowptr[t] = lo;
}

// ---------------------------------------------------------------------------
// 2) GEMM via HMMA tensor cores (R9 version, measured 18.7us): 128 threads,
//    block tile 128x64, warp tile 32x64, full K=128 staged in smem.
// ---------------------------------------------------------------------------
#define XS_HALVES (128 * 128)   // 32768 B
#define WS_HALVES (128 * 64)    // 16384 B

__global__ __launch_bounds__(128) void gemm_kernel(const float* __restrict__ X,
                                                   const float* __restrict__ W,
                                                   const float* __restrict__ b) {
    __shared__ __half Xs[XS_HALVES];   // [row][k], swizzled 16B chunks
    __shared__ __half Ws[WS_HALVES];   // [k][n],  swizzled 16B chunks

    const int tid    = threadIdx.x;
    const int lane   = tid & 31;
    const int warpId = tid >> 5;
    const int rowBase = blockIdx.x * 128;

    #pragma unroll
    for (int i = 0; i < 32; ++i) {
        const int linear = tid + 128 * i;
        const int row = linear >> 5;
        const int c   = linear & 31;
        const int gr  = rowBase + row;
        float4 v = (gr < N_NODES) ? __ldg((const float4*)&X[(size_t)gr * IN_SIZE + 4 * c])
                                  : make_float4(0.f, 0.f, 0.f, 0.f);
        __align__(8) __half2 h[2];
        h[0] = __floats2half2_rn(v.x, v.y);
        h[1] = __floats2half2_rn(v.z, v.w);
        const int chunk = ((c >> 1) ^ (row & 7));
        *(uint2*)&Xs[row * 128 + chunk * 8 + 4 * (c & 1)] = *(const uint2*)h;
    }

    #pragma unroll
    for (int i = 0; i < 16; ++i) {
        const int linear = tid + 128 * i;
        const int k = linear >> 4;
        const int c = linear & 15;
        float4 v = __ldg((const float4*)&W[(size_t)k * OUT_SIZE + 4 * c]);
        __align__(8) __half2 h[2];
        h[0] = __floats2half2_rn(v.x, v.y);
        h[1] = __floats2half2_rn(v.z, v.w);
        const int chunk = ((c >> 1) ^ (k & 7));
        *(uint2*)&Ws[k * 64 + chunk * 8 + 4 * (c & 1)] = *(const uint2*)h;
    }
    __syncthreads();

    const int wr = warpId * 32;
    float d[2][8][4];
    #pragma unroll
    for (int rt = 0; rt < 2; ++rt)
        #pragma unroll
        for (int nt = 0; nt < 8; ++nt)
            #pragma unroll
            for (int q = 0; q < 4; ++q) d[rt][nt][q] = 0.f;

    #pragma unroll
    for (int ks = 0; ks < 8; ++ks) {
        unsigned a[2][4];
        #pragma unroll
        for (int rt = 0; rt < 2; ++rt) {
            const int row = wr + rt * 16 + (lane & 15);
            const int chunk = (ks * 2 + (lane >> 4)) ^ (row & 7);
            const unsigned addr =
                (unsigned)__cvta_generic_to_shared(&Xs[row * 128 + chunk * 8]);
            asm volatile("ldmatrix.sync.aligned.m8n8.x4.shared.b16 {%0,%1,%2,%3}, [%4];"
                         : "=r"(a[rt][0]), "=r"(a[rt][1]), "=r"(a[rt][2]), "=r"(a[rt][3])
                         : "r"(addr));
        }
        #pragma unroll
        for (int np = 0; np < 4; ++np) {
            const int k = ks * 16 + (lane & 7) + ((lane >> 3) & 1) * 8;
            const int chunk = (np * 2 + (lane >> 4)) ^ (k & 7);
            const unsigned addr =
                (unsigned)__cvta_generic_to_shared(&Ws[k * 64 + chunk * 8]);
            unsigned bf[4];
            asm volatile("ldmatrix.sync.aligned.m8n8.x4.trans.shared.b16 {%0,%1,%2,%3}, [%4];"
                         : "=r"(bf[0]), "=r"(bf[1]), "=r"(bf[2]), "=r"(bf[3])
                         : "r"(addr));
            #pragma unroll
            for (int rt = 0; rt < 2; ++rt) {
                asm volatile(
                    "mma.sync.aligned.m16n8k16.row.col.f32.f16.f16.f32 "
                    "{%0,%1,%2,%3}, {%4,%5,%6,%7}, {%8,%9}, {%0,%1,%2,%3};"
                    : "+f"(d[rt][2 * np][0]), "+f"(d[rt][2 * np][1]),
                      "+f"(d[rt][2 * np][2]), "+f"(d[rt][2 * np][3])
                    : "r"(a[rt][0]), "r"(a[rt][1]), "r"(a[rt][2]), "r"(a[rt][3]),
                      "r"(bf[0]), "r"(bf[1]));
                asm volatile(
                    "mma.sync.aligned.m16n8k16.row.col.f32.f16.f16.f32 "
                    "{%0,%1,%2,%3}, {%4,%5,%6,%7}, {%8,%9}, {%0,%1,%2,%3};"
                    : "+f"(d[rt][2 * np + 1][0]), "+f"(d[rt][2 * np + 1][1]),
                      "+f"(d[rt][2 * np + 1][2]), "+f"(d[rt][2 * np + 1][3])
                    : "r"(a[rt][0]), "r"(a[rt][1]), "r"(a[rt][2]), "r"(a[rt][3]),
                      "r"(bf[2]), "r"(bf[3]));
            }
        }
    }

    float2 bias2[8];
    #pragma unroll
    for (int nt = 0; nt < 8; ++nt)
        bias2[nt] = __ldg(&((const float2*)b)[nt * 4 + (lane & 3)]);

    #pragma unroll
    for (int rt = 0; rt < 2; ++rt) {
        const int r0 = rowBase + wr + rt * 16 + (lane >> 2);
        const int r1 = r0 + 8;
        #pragma unroll
        for (int nt = 0; nt < 8; ++nt) {
            const int h2idx = nt * 4 + (lane & 3);
            if (r0 < N_NODES)
                g_h0[(size_t)r0 * 32 + h2idx] =
                    __floats2half2_rn(d[rt][nt][0] + bias2[nt].x,
                                      d[rt][nt][1] + bias2[nt].y);
            if (r1 < N_NODES)
                g_h0[(size_t)r1 * 32 + h2idx] =
                    __floats2half2_rn(d[rt][nt][2] + bias2[nt].x,
                                      d[rt][nt][3] + bias2[nt].y);
        }
    }
}

// reinterpret uint4 component j as half2
__device__ __forceinline__ __half2 h2c(unsigned w) {
    return *reinterpret_cast<__half2*>(&w);
}

// accumulate 8 halves (one uint4) into float[8]
__device__ __forceinline__ void acc16(float* a, uint4 u) {
    const float2 f0 = __half22float2(h2c(u.x));
    const float2 f1 = __half22float2(h2c(u.y));
    const float2 f2 = __half22float2(h2c(u.z));
    const float2 f3 = __half22float2(h2c(u.w));
    a[0] += f0.x; a[1] += f0.y; a[2] += f1.x; a[3] += f1.y;
    a[4] += f2.x; a[5] += f2.y; a[6] += f3.x; a[7] += f3.y;
}

// ---------------------------------------------------------------------------
// 3) Propagation: FOUR nodes per warp (quarter-warp of 8 lanes per node).
//    Edges processed in groups of 4: fp16 HADD2 pair-tree (depth 2) then one
//    convert+FADD into the fp32 accumulator -> ~2x fewer issue slots per edge.
//    new[t] = (deg>0) ? (in[t] + sum in[src[e]]) / (deg+1) : 0
//    stage 0: g_h0 -> g_h1 (fp16);  stage 1: g_h1 -> d_out (fp32, ReLU)
// ---------------------------------------------------------------------------
__global__ __launch_bounds__(256) void prop_kernel(const void* __restrict__ src_any,
                                                   float* __restrict__ dout, int stage) {
    const int is64 = warp_detect64(src_any);   // full warp active here
    const int gw   = (blockIdx.x * blockDim.x + threadIdx.x) >> 5;
    const int lane = threadIdx.x & 31;
    const int q    = lane >> 3;        // quarter 0..3
    const int ln8  = lane & 7;         // lane within quarter
    const int t    = gw * 4 + q;
    if (t >= N_NODES) return;

    const uint4* __restrict__ in = (stage == 0) ? (const uint4*)g_h0 : (const uint4*)g_h1;
    const long long* __restrict__ s64 = (const long long*)src_any;
    const int*       __restrict__ s32 = (const int*)src_any;

    const int start = __ldg(&g_rowptr[t]);
    const int end   = __ldg(&g_rowptr[t + 1]);
    const int deg   = end - start;

    float a[8] = {0.f, 0.f, 0.f, 0.f, 0.f, 0.f, 0.f, 0.f};

    if (deg > 0) {
        int e = start;
        // groups of 4 edges: fp16 pair tree, one fp32 accumulate per group
        for (; e + 4 <= end; e += 4) {
            const int i0 = is64 ? (int)__ldg(&s64[e + 0]) : __ldg(&s32[e + 0]);
            const int i1 = is64 ? (int)__ldg(&s64[e + 1]) : __ldg(&s32[e + 1]);
            const int i2 = is64 ? (int)__ldg(&s64[e + 2]) : __ldg(&s32[e + 2]);
            const int i3 = is64 ? (int)__ldg(&s64[e + 3]) : __ldg(&s32[e + 3]);
            const uint4 u0 = __ldg(&in[(size_t)i0 * 8 + ln8]);
            const uint4 u1 = __ldg(&in[(size_t)i1 * 8 + ln8]);
            const uint4 u2 = __ldg(&in[(size_t)i2 * 8 + ln8]);
            const uint4 u3 = __ldg(&in[(size_t)i3 * 8 + ln8]);

            const __half2 s0 = __hadd2(__hadd2(h2c(u0.x), h2c(u1.x)),
                                       __hadd2(h2c(u2.x), h2c(u3.x)));
            const __half2 s1 = __hadd2(__hadd2(h2c(u0.y), h2c(u1.y)),
                                       __hadd2(h2c(u2.y), h2c(u3.y)));
            const __half2 s2 = __hadd2(__hadd2(h2c(u0.z), h2c(u1.z)),
                                       __hadd2(h2c(u2.z), h2c(u3.z)));
            const __half2 s3 = __hadd2(__hadd2(h2c(u0.w), h2c(u1.w)),
                                       __hadd2(h2c(u2.w), h2c(u3.w)));
            const float2 f0 = __half22float2(s0);
            const float2 f1 = __half22float2(s1);
            const float2 f2 = __half22float2(s2);
            const float2 f3 = __half22float2(s3);
            a[0] += f0.x; a[1] += f0.y; a[2] += f1.x; a[3] += f1.y;
            a[4] += f2.x; a[5] += f2.y; a[6] += f3.x; a[7] += f3.y;
        }
        // remainder (0-3 edges)
        for (; e < end; ++e) {
            const int s = is64 ? (int)__ldg(&s64[e]) : __ldg(&s32[e]);
            acc16(a, __ldg(&in[(size_t)s * 8 + ln8]));
        }

        // own contribution + scale
        acc16(a, __ldg(&in[(size_t)t * 8 + ln8]));
        const float sc = 1.0f / (float)(deg + 1);
        #pragma unroll
        for (int i = 0; i < 8; ++i) a[i] *= sc;
    }
    // deg==0: a stays zero

    if (stage == 0) {
        __align__(16) __half2 h[4];
        h[0] = __floats2half2_rn(a[0], a[1]);
        h[1] = __floats2half2_rn(a[2], a[3]);
        h[2] = __floats2half2_rn(a[4], a[5]);
        h[3] = __floats2half2_rn(a[6], a[7]);
        ((uint4*)g_h1)[(size_t)t * 8 + ln8] = *(const uint4*)h;
    } else {
        #pragma unroll
        for (int i = 0; i < 8; ++i) a[i] = fmaxf(a[i], 0.f);
        *(float4*)&dout[(size_t)t * 64 + ln8 * 8]     = make_float4(a[0], a[1], a[2], a[3]);
        *(float4*)&dout[(size_t)t * 64 + ln8 * 8 + 4] = make_float4(a[4], a[5], a[6], a[7]);
    }
}

// ---------------------------------------------------------------------------
// Launch. Inputs (metadata order): data, W, b, src_idx, tgt_idx
// ---------------------------------------------------------------------------
extern "C" void kernel_launch(void* const* d_in, const int* in_sizes, int n_in,
                              void* d_out, int out_size) {
    const float* X = (const float*)d_in[0];
    const float* W = (const float*)d_in[1];
    const float* b = (const float*)d_in[2];
    const void*  src = d_in[3];
    const void*  tgt = d_in[4];
    float* out = (float*)d_out;

    rowptr_kernel<<<(N_NODES + 1 + 255) / 256, 256>>>(src, tgt);
    gemm_kernel<<<(N_NODES + 127) / 128, 128>>>(X, W, b);
    const int propBlocks = (N_NODES + 31) / 32;   // 4 nodes/warp, 8 warps/block
    prop_kernel<<<propBlocks, 256>>>(src, out, 0);
    prop_kernel<<<propBlocks, 256>>>(src, out, 1);
}